// round 15
// baseline (speedup 1.0000x reference)
#include <cuda_runtime.h>
#include <stdint.h>

// Problem constants (fixed by the reference setup)
#define Bn 16
#define Pn 784
#define Dn 10000
#define Ln 1000
#define Cn 10

#define WSTRIDE 320    // padded words per row
#define NROWS   (Ln + Pn)            // 1784 packed rows
#define NSS     5      // 5 superslabs of 64 words
#define NCH     7      // 7 pixel chunks of 112 (8 warps x 14)
#define NBP     8      // 8 batch pairs
#define NGROUP  (NBP * NSS)          // 40 (bp, ss) groups
#define NMAIN   (NGROUP * NCH)       // 280 main CTAs
#define NPACK   296                  // pack CTAs (2/SM)
#define SS_TARGET (NROWS * 4)        // 7136 tasks complete a superslab

// Scratch (allocation-free: device globals)
__device__ uint32_t g_vbits[Ln * WSTRIDE];     // sign bits of value_weight
__device__ uint32_t g_pbits[Pn * WSTRIDE];     // sign bits of position_weight
__device__ uint32_t g_idx2[NBP * Pn];          // packed level idx pair (lo|hi<<16)
__device__ uint2    g_chunk[NMAIN * 2 * 7 * 32]; // 7-plane chunk partials
__device__ float    g_partial[NSS * Bn * Cn];
__device__ int      g_ready[NSS];              // per-superslab pack completions
__device__ int      g_gctr[NGROUP];            // per-group arrival counters
__device__ int      g_ctr2;                    // group completion counter

// ---------------------------------------------------------------------------
__device__ __forceinline__ void fadd(uint32_t a, uint32_t b, uint32_t cin,
                                     uint32_t& s, uint32_t& cout)
{
    uint32_t t = a ^ b;
    s    = t ^ cin;
    cout = (a & b) | (cin & t);
}

// 7:3 compress t[0..6] and merge into 4-plane counter cp[0..3] (max 14)
__device__ __forceinline__ void csa7_merge4(const uint32_t* t, uint32_t* cp)
{
    uint32_t s1, c1, s2, c2, s3, c3, s4, c4;
    fadd(t[0], t[1], t[2], s1, c1);
    fadd(t[3], t[4], t[5], s2, c2);
    fadd(s1,  s2,  t[6],  s3, c3);
    fadd(c1,  c2,  c3,    s4, c4);
    uint32_t carry = cp[0] & s3; cp[0] ^= s3;
    uint32_t s, co;
    fadd(cp[1], s4, carry, s, co); cp[1] = s; carry = co;
    fadd(cp[2], c4, carry, s, co); cp[2] = s; carry = co;
    cp[3] ^= carry;
}

// enc bit = 1 iff count < 392 (392 = 0b0110001000), 10 bit-planes
__device__ __forceinline__ uint32_t thr392(const uint32_t* c)
{
    uint32_t eq = ~0u, lt = 0u;
    eq &= ~c[9];
    lt |= eq & ~c[8]; eq &= c[8];
    lt |= eq & ~c[7]; eq &= c[7];
    eq &= ~c[6]; eq &= ~c[5]; eq &= ~c[4];
    lt |= eq & ~c[3];
    return lt;
}

// ---------------------------------------------------------------------------
// Pack side (bids 0..NPACK-1): idx pairs + sign packing, SUPERSLAB-MAJOR task
// order (task = s*NROWS + row). After each task the warp publishes completion
// to g_ready[s>>2] (syncwarp -> lane0 fence + red). Permuted bit layout:
// word w, bit l <-> dim d = (w>>2)*128 + l*4 + (w&3).
// ---------------------------------------------------------------------------
__device__ void pack_side(const float* __restrict__ x,
                          const float* __restrict__ posw,
                          const float* __restrict__ valw)
{
    const int tid     = blockIdx.x * 256 + threadIdx.x;
    const int nthread = NPACK * 256;

    // packed level indices (written BEFORE any task red in program order)
    for (int i = tid; i < NBP * Pn; i += nthread) {
        int bp = i / Pn, p = i - bp * Pn;
        int qa = (int)rintf(x[(2 * bp)     * Pn + p] * 999.0f);
        int qb = (int)rintf(x[(2 * bp + 1) * Pn + p] * 999.0f);
        qa = min(max(qa, 0), Ln - 1);
        qb = min(max(qb, 0), Ln - 1);
        g_idx2[i] = (uint32_t)qa | ((uint32_t)qb << 16);
    }

    const int lane   = threadIdx.x & 31;
    const int warpId = tid >> 5;
    const int nWarps = NPACK * 8;            // 2368
    const int totalTasks = 20 * NROWS;       // superslab-major

    for (int task = warpId; task < totalTasks; task += nWarps) {
        int s   = task / NROWS;
        int row = task - s * NROWS;
        const float* src;
        uint32_t* dst;
        if (row < Ln) {
            src = valw + (size_t)row * Dn;
            dst = g_vbits + row * WSTRIDE;
        } else {
            src = posw + (size_t)(row - Ln) * Dn;
            dst = g_pbits + (row - Ln) * WSTRIDE;
        }

        uint32_t myword = 0;
        if (s < 19) {
            float4 v0 = *reinterpret_cast<const float4*>(src + s * 512 +   0 + lane * 4);
            float4 v1 = *reinterpret_cast<const float4*>(src + s * 512 + 128 + lane * 4);
            float4 v2 = *reinterpret_cast<const float4*>(src + s * 512 + 256 + lane * 4);
            float4 v3 = *reinterpret_cast<const float4*>(src + s * 512 + 384 + lane * 4);
#define PK(sub, vv)                                                          \
            {                                                                \
                uint32_t b0 = __ballot_sync(0xffffffffu, (vv).x < 0.0f);     \
                uint32_t b1 = __ballot_sync(0xffffffffu, (vv).y < 0.0f);     \
                uint32_t b2 = __ballot_sync(0xffffffffu, (vv).z < 0.0f);     \
                uint32_t b3 = __ballot_sync(0xffffffffu, (vv).w < 0.0f);     \
                if (lane == (sub)*4 + 0) myword = b0;                        \
                if (lane == (sub)*4 + 1) myword = b1;                        \
                if (lane == (sub)*4 + 2) myword = b2;                        \
                if (lane == (sub)*4 + 3) myword = b3;                        \
            }
            PK(0, v0) PK(1, v1) PK(2, v2) PK(3, v3)
#undef PK
        } else {
            // tail task (dims 9728..10239): per-lane validity
#pragma unroll
            for (int sub = 0; sub < 4; sub++) {
                int d0 = s * 512 + sub * 128 + lane * 4;
                bool valid = d0 < Dn;            // Dn % 4 == 0
                float4 v = make_float4(0.f, 0.f, 0.f, 0.f);
                if (valid) v = *reinterpret_cast<const float4*>(src + d0);
                uint32_t b0 = __ballot_sync(0xffffffffu, valid && v.x < 0.0f);
                uint32_t b1 = __ballot_sync(0xffffffffu, valid && v.y < 0.0f);
                uint32_t b2 = __ballot_sync(0xffffffffu, valid && v.z < 0.0f);
                uint32_t b3 = __ballot_sync(0xffffffffu, valid && v.w < 0.0f);
                if (lane == sub * 4 + 0) myword = b0;
                if (lane == sub * 4 + 1) myword = b1;
                if (lane == sub * 4 + 2) myword = b2;
                if (lane == sub * 4 + 3) myword = b3;
            }
        }
        if (lane < 16) dst[s * 16 + lane] = myword;      // coalesced 64B

        __syncwarp();                        // order lanes' stores before publish
        if (lane == 0) {
            __threadfence();                 // release (covers idx2 + this task)
            atomicAdd(&g_ready[s >> 2], 1);  // fire-and-forget RED
        }
    }
}

// ---------------------------------------------------------------------------
// Main side (bids NPACK..): unit u = (ss-major) spin-waits for its superslab,
// then runs the R11 gather: lane = word-pair (uint2), pbits shared across the
// batch pair, 7:3 CSA -> 3-round tree -> chunk partial; 7th CTA of the group
// does threshold + coalesced classify; 40th group completion writes out and
// resets g_ready for the next replay. Deterministic; int atomics only.
// ---------------------------------------------------------------------------
__device__ void main_side(int u, const float* __restrict__ cw,
                          float* __restrict__ out)
{
    const int ss  = u / (NBP * NCH);             // ss-major: earliest wait ss0
    const int r0  = u - ss * (NBP * NCH);
    const int bp  = r0 / NCH;
    const int ch  = r0 - bp * NCH;
    const int grp = bp * NSS + ss;
    const int cid = grp * NCH + ch;              // chunk-partial slot
    const int tid = threadIdx.x;
    const int lane = tid & 31;
    const int wsub = tid >> 5;                   // 0..7

    __shared__ uint32_t sIdx2[112];
    __shared__ uint2    sBuf[4][2][7][32];       // [src][b][plane][lane]
    __shared__ uint32_t sEnc[2][64];
    __shared__ int      sDoB, sLast;

    // ---- wait for this superslab's pack completion ----
    if (tid == 0) {
        while (*(volatile int*)&g_ready[ss] < SS_TARGET) __nanosleep(128);
        __threadfence();                         // acquire packed tables + idx2
    }
    __syncthreads();

    if (tid < 112) sIdx2[tid] = g_idx2[bp * Pn + ch * 112 + tid];
    __syncthreads();

    const int wbase = ss * 64 + 2 * lane;        // first word of lane's pair
    const int p0    = ch * 112 + wsub * 14;      // global first pixel of warp

    uint32_t cnt[2][2][4];                       // [batch][comp][plane], <=14
#pragma unroll
    for (int b = 0; b < 2; b++)
#pragma unroll
        for (int c = 0; c < 2; c++)
#pragma unroll
            for (int j = 0; j < 4; j++) cnt[b][c][j] = 0u;

#pragma unroll
    for (int g = 0; g < 2; g++) {                // 2 groups of 7 pixels
        const int pg = p0 + g * 7;
        const int lg = wsub * 14 + g * 7;        // local pixel in chunk
        uint32_t pr[7]; uint2 q[7], va[7], vb[7];
#pragma unroll
        for (int k = 0; k < 7; k++) pr[k] = sIdx2[lg + k];
#pragma unroll
        for (int k = 0; k < 7; k++)
            q[k] = __ldg(reinterpret_cast<const uint2*>(g_pbits + (pg + k) * WSTRIDE + wbase));
#pragma unroll
        for (int k = 0; k < 7; k++)
            va[k] = __ldg(reinterpret_cast<const uint2*>(g_vbits + (pr[k] & 0xffffu) * WSTRIDE + wbase));
#pragma unroll
        for (int k = 0; k < 7; k++)
            vb[k] = __ldg(reinterpret_cast<const uint2*>(g_vbits + (pr[k] >> 16) * WSTRIDE + wbase));

        uint32_t t[7];
#pragma unroll
        for (int k = 0; k < 7; k++) t[k] = va[k].x ^ q[k].x;
        csa7_merge4(t, cnt[0][0]);
#pragma unroll
        for (int k = 0; k < 7; k++) t[k] = va[k].y ^ q[k].y;
        csa7_merge4(t, cnt[0][1]);
#pragma unroll
        for (int k = 0; k < 7; k++) t[k] = vb[k].x ^ q[k].x;
        csa7_merge4(t, cnt[1][0]);
#pragma unroll
        for (int k = 0; k < 7; k++) t[k] = vb[k].y ^ q[k].y;
        csa7_merge4(t, cnt[1][1]);
    }

    // ---- 3-round tree reduction across 8 warps: 4 -> 7 planes ----
    uint32_t a[2][2][7];
#pragma unroll
    for (int b = 0; b < 2; b++)
#pragma unroll
        for (int c = 0; c < 2; c++) {
#pragma unroll
            for (int j = 0; j < 4; j++) a[b][c][j] = cnt[b][c][j];
            a[b][c][4] = a[b][c][5] = a[b][c][6] = 0u;
        }

#pragma unroll
    for (int r = 0; r < 3; r++) {
        const int half = 4 >> r;                 // 4,2,1 readers
        const int np   = 4 + r;                  // planes valid in sources
        if (wsub >= half && wsub < 2 * half) {
#pragma unroll
            for (int b = 0; b < 2; b++)
#pragma unroll
                for (int j = 0; j < 7; j++)
                    if (j < np)
                        sBuf[wsub - half][b][j][lane] = make_uint2(a[b][0][j], a[b][1][j]);
        }
        __syncthreads();
        if (wsub < half) {
#pragma unroll
            for (int b = 0; b < 2; b++) {
                uint32_t cx = 0u, cy = 0u;
#pragma unroll
                for (int j = 0; j < 7; j++) {
                    if (j < np) {
                        uint2 v = sBuf[wsub][b][j][lane];
                        uint32_t s, co;
                        fadd(a[b][0][j], v.x, cx, s, co); a[b][0][j] = s; cx = co;
                        fadd(a[b][1][j], v.y, cy, s, co); a[b][1][j] = s; cy = co;
                    } else if (j == np) {
                        a[b][0][j] = cx; a[b][1][j] = cy;
                    }
                }
            }
        }
        __syncthreads();
    }

    if (wsub == 0) {                             // write 7-plane chunk partial
#pragma unroll
        for (int b = 0; b < 2; b++)
#pragma unroll
            for (int j = 0; j < 7; j++)
                g_chunk[((cid * 2 + b) * 7 + j) * 32 + lane] =
                    make_uint2(a[b][0][j], a[b][1][j]);
    }
    __syncthreads();

    // ---- group arrival: 7th CTA of this (bp,ss) runs phase B ----
    if (tid == 0) {
        __threadfence();
        int prev = atomicAdd(&g_gctr[grp], 1);
        sDoB = (prev == NCH - 1);
        if (sDoB) g_gctr[grp] = 0;               // reset for next replay
    }
    __syncthreads();
    if (!sDoB) return;

    __threadfence();                             // acquire peer chunk partials

    // ---- phase B: warps 0,1 (one per batch) sum 7 chunks -> enc ----
    if (wsub < 2) {
        uint32_t s[2][10];
#pragma unroll
        for (int c = 0; c < 2; c++)
#pragma unroll
            for (int j = 0; j < 10; j++) s[c][j] = 0u;
#pragma unroll
        for (int c2 = 0; c2 < NCH; c2++) {
            const int uc = grp * NCH + c2;       // chunk-partial slot
            uint32_t cx = 0u, cy = 0u;
#pragma unroll
            for (int j = 0; j < 7; j++) {
                uint2 v = g_chunk[((uc * 2 + wsub) * 7 + j) * 32 + lane];
                uint32_t ss2, co;
                fadd(s[0][j], v.x, cx, ss2, co); s[0][j] = ss2; cx = co;
                fadd(s[1][j], v.y, cy, ss2, co); s[1][j] = ss2; cy = co;
            }
#pragma unroll
            for (int j = 7; j < 10; j++) {
                uint32_t nc = s[0][j] ^ cx; cx &= s[0][j]; s[0][j] = nc;
                nc = s[1][j] ^ cy; cy &= s[1][j]; s[1][j] = nc;
            }
        }
        sEnc[wsub][2 * lane]     = thr392(s[0]);
        sEnc[wsub][2 * lane + 1] = thr392(s[1]);
    }
    __syncthreads();

    // ---- coalesced classify: uu = b*10+c over dims [ss*2048, +2048) ----
    for (int uu = wsub; uu < 2 * Cn; uu += 8) {
        const int b = uu / Cn, c = uu - (uu / Cn) * Cn;
        const float* __restrict__ wrow = cw + c * Dn + ss * 2048;
        float acc = 0.0f;
#pragma unroll
        for (int i = 0; i < 16; i++) {
            int d0 = ss * 2048 + i * 128 + lane * 4;
            if (d0 < Dn) {                       // Dn%4==0 -> whole float4 valid
                uint32_t w0 = sEnc[b][i * 4 + 0];
                uint32_t w1 = sEnc[b][i * 4 + 1];
                uint32_t w2 = sEnc[b][i * 4 + 2];
                uint32_t w3 = sEnc[b][i * 4 + 3];
                float4 v = *reinterpret_cast<const float4*>(wrow + i * 128 + lane * 4);
                acc += ((w0 >> lane) & 1u) ? v.x : -v.x;
                acc += ((w1 >> lane) & 1u) ? v.y : -v.y;
                acc += ((w2 >> lane) & 1u) ? v.z : -v.z;
                acc += ((w3 >> lane) & 1u) ? v.w : -v.w;
            }
        }
#pragma unroll
        for (int off = 16; off >= 1; off >>= 1)  // deterministic fixed order
            acc += __shfl_xor_sync(0xffffffffu, acc, off);
        if (lane == 0) g_partial[(ss * Bn + (bp * 2 + b)) * Cn + c] = acc;
    }

    // ---- 40th group completion writes out + resets replay state ----
    __syncthreads();
    if (tid == 0) {
        __threadfence();
        int prev = atomicAdd(&g_ctr2, 1);
        sLast = (prev == NGROUP - 1);
    }
    __syncthreads();
    if (sLast) {
        __threadfence();
        if (tid < Bn * Cn) {
            float s = 0.0f;
#pragma unroll
            for (int sl = 0; sl < NSS; sl++) s += g_partial[sl * Bn * Cn + tid];
            out[tid] = s;
        }
        if (tid < NSS) g_ready[tid] = 0;         // reset for next replay
        if (tid == 0)  g_ctr2 = 0;
    }
}

// ---------------------------------------------------------------------------
__global__ void __launch_bounds__(256, 4) hdc_olap_kernel(
    const float* __restrict__ x,    const float* __restrict__ posw,
    const float* __restrict__ valw, const float* __restrict__ cw,
    float* __restrict__ out)
{
    if (blockIdx.x < NPACK) pack_side(x, posw, valw);
    else                    main_side(blockIdx.x - NPACK, cw, out);
}

// ---------------------------------------------------------------------------
extern "C" void kernel_launch(void* const* d_in, const int* in_sizes, int n_in,
                              void* d_out, int out_size)
{
    const float* x    = (const float*)d_in[0];   // [16,28,28]
    const float* posw = (const float*)d_in[1];   // [784,10000]
    const float* valw = (const float*)d_in[2];   // [1000,10000]
    const float* cw   = (const float*)d_in[3];   // [10,10000]
    float* out = (float*)d_out;                  // [16,10]

    hdc_olap_kernel<<<NPACK + NMAIN, 256>>>(x, posw, valw, cw, out);
}

// round 16
// speedup vs baseline: 2.7304x; 2.7304x over previous
#include <cuda_runtime.h>
#include <stdint.h>

// Problem constants (fixed by the reference setup)
#define Bn 16
#define Pn 784
#define Dn 10000
#define Ln 1000
#define Cn 10

#define WSTRIDE 320    // padded words per row
#define NSS     5      // 5 superslabs of 64 words
#define NCH     7      // 7 pixel chunks of 112 (8 warps x 14)
#define NBP     8      // 8 batch pairs
#define NGROUP  (NBP * NSS)          // 40 (bp, ss) groups
#define NMAIN   (NGROUP * NCH)       // 280 main CTAs

// Scratch (allocation-free: device globals)
__device__ uint32_t g_vbits[Ln * WSTRIDE];     // sign bits of value_weight
__device__ uint32_t g_pbits[Pn * WSTRIDE];     // sign bits of position_weight
__device__ uint32_t g_idx2[NBP * Pn];          // packed level idx pair (lo|hi<<16)
__device__ uint2    g_chunk[NMAIN * 2 * 7 * 32]; // 7-plane chunk partials
__device__ float    g_partial[NSS * Bn * Cn];
__device__ int      g_gctr[NGROUP];            // per-group arrival counters
__device__ int      g_ctr2;                    // group completion counter

// ---------------------------------------------------------------------------
// Kernel 1: packed idx pairs + sign packing of both bipolar tables.
// Warp-task = 1024 dims: 8 lane-contiguous float4 loads (fully coalesced,
// row-major task order preserves DRAM page locality), FSETP -> ballot -> sel,
// 32 words per task. Word w = s*32 + sub*4 + k keeps the global layout
// d = (w>>2)*128 + l*4 + (w&3) identical to previous rounds.
// ---------------------------------------------------------------------------
__global__ void __launch_bounds__(256) pack_kernel(const float* __restrict__ x,
                                                   const float* __restrict__ posw,
                                                   const float* __restrict__ valw)
{
    const int tid     = blockIdx.x * blockDim.x + threadIdx.x;
    const int nthread = gridDim.x * blockDim.x;

    // packed level indices: idx = clamp(rint(x*999), 0, 999)  (half-to-even)
    for (int i = tid; i < NBP * Pn; i += nthread) {
        int bp = i / Pn, p = i - bp * Pn;
        int qa = (int)rintf(x[(2 * bp)     * Pn + p] * 999.0f);
        int qb = (int)rintf(x[(2 * bp + 1) * Pn + p] * 999.0f);
        qa = min(max(qa, 0), Ln - 1);
        qb = min(max(qb, 0), Ln - 1);
        g_idx2[i] = (uint32_t)qa | ((uint32_t)qb << 16);
    }

    const int lane   = threadIdx.x & 31;
    const int warpId = tid >> 5;
    const int nWarps = nthread >> 5;
    const int totalTasks = (Ln + Pn) * 10;   // 10 x 1024-dim tasks per row

    for (int task = warpId; task < totalTasks; task += nWarps) {
        int row = task / 10;
        int s   = task - row * 10;
        const float* src;
        uint32_t* dst;
        if (row < Ln) {
            src = valw + (size_t)row * Dn;
            dst = g_vbits + row * WSTRIDE;
        } else {
            src = posw + (size_t)(row - Ln) * Dn;
            dst = g_pbits + (row - Ln) * WSTRIDE;
        }

        uint32_t myword = 0;
        if (s < 9) {
            // fast path: all 1024 dims valid; 8 independent loads (MLP=8)
            float4 v0 = *reinterpret_cast<const float4*>(src + s * 1024 +   0 + lane * 4);
            float4 v1 = *reinterpret_cast<const float4*>(src + s * 1024 + 128 + lane * 4);
            float4 v2 = *reinterpret_cast<const float4*>(src + s * 1024 + 256 + lane * 4);
            float4 v3 = *reinterpret_cast<const float4*>(src + s * 1024 + 384 + lane * 4);
            float4 v4 = *reinterpret_cast<const float4*>(src + s * 1024 + 512 + lane * 4);
            float4 v5 = *reinterpret_cast<const float4*>(src + s * 1024 + 640 + lane * 4);
            float4 v6 = *reinterpret_cast<const float4*>(src + s * 1024 + 768 + lane * 4);
            float4 v7 = *reinterpret_cast<const float4*>(src + s * 1024 + 896 + lane * 4);
#define PK(sub, vv)                                                          \
            {                                                                \
                uint32_t b0 = __ballot_sync(0xffffffffu, (vv).x < 0.0f);     \
                uint32_t b1 = __ballot_sync(0xffffffffu, (vv).y < 0.0f);     \
                uint32_t b2 = __ballot_sync(0xffffffffu, (vv).z < 0.0f);     \
                uint32_t b3 = __ballot_sync(0xffffffffu, (vv).w < 0.0f);     \
                if (lane == (sub)*4 + 0) myword = b0;                        \
                if (lane == (sub)*4 + 1) myword = b1;                        \
                if (lane == (sub)*4 + 2) myword = b2;                        \
                if (lane == (sub)*4 + 3) myword = b3;                        \
            }
            PK(0, v0) PK(1, v1) PK(2, v2) PK(3, v3)
            PK(4, v4) PK(5, v5) PK(6, v6) PK(7, v7)
#undef PK
        } else {
            // tail task (dims 9216..10239): per-lane validity
#pragma unroll
            for (int sub = 0; sub < 8; sub++) {
                int d0 = s * 1024 + sub * 128 + lane * 4;
                bool valid = d0 < Dn;            // Dn % 4 == 0
                float4 v = make_float4(0.f, 0.f, 0.f, 0.f);
                if (valid) v = *reinterpret_cast<const float4*>(src + d0);
                uint32_t b0 = __ballot_sync(0xffffffffu, valid && v.x < 0.0f);
                uint32_t b1 = __ballot_sync(0xffffffffu, valid && v.y < 0.0f);
                uint32_t b2 = __ballot_sync(0xffffffffu, valid && v.z < 0.0f);
                uint32_t b3 = __ballot_sync(0xffffffffu, valid && v.w < 0.0f);
                if (lane == sub * 4 + 0) myword = b0;
                if (lane == sub * 4 + 1) myword = b1;
                if (lane == sub * 4 + 2) myword = b2;
                if (lane == sub * 4 + 3) myword = b3;
            }
        }
        dst[s * 32 + lane] = myword;             // coalesced 128B per warp
    }
}

// ---------------------------------------------------------------------------
__device__ __forceinline__ void fadd(uint32_t a, uint32_t b, uint32_t cin,
                                     uint32_t& s, uint32_t& cout)
{
    uint32_t t = a ^ b;
    s    = t ^ cin;
    cout = (a & b) | (cin & t);
}

// 7:3 compress t[0..6] and merge into 4-plane counter cp[0..3] (max 14)
__device__ __forceinline__ void csa7_merge4(const uint32_t* t, uint32_t* cp)
{
    uint32_t s1, c1, s2, c2, s3, c3, s4, c4;
    fadd(t[0], t[1], t[2], s1, c1);
    fadd(t[3], t[4], t[5], s2, c2);
    fadd(s1,  s2,  t[6],  s3, c3);
    fadd(c1,  c2,  c3,    s4, c4);
    uint32_t carry = cp[0] & s3; cp[0] ^= s3;
    uint32_t s, co;
    fadd(cp[1], s4, carry, s, co); cp[1] = s; carry = co;
    fadd(cp[2], c4, carry, s, co); cp[2] = s; carry = co;
    cp[3] ^= carry;
}

// enc bit = 1 iff count < 392 (392 = 0b0110001000), 10 bit-planes
__device__ __forceinline__ uint32_t thr392(const uint32_t* c)
{
    uint32_t eq = ~0u, lt = 0u;
    eq &= ~c[9];
    lt |= eq & ~c[8]; eq &= c[8];
    lt |= eq & ~c[7]; eq &= c[7];
    eq &= ~c[6]; eq &= ~c[5]; eq &= ~c[4];
    lt |= eq & ~c[3];
    return lt;
}

// ---------------------------------------------------------------------------
// Kernel 2 (R11 body, session-best 14.9us): CTA = (batch-pair, superslab of
// 64 words, chunk of 112 pixels), 256 threads = 8 warps x 14 px. Lane holds
// a word pair (uint2, LDG.64); pbits loaded once per pixel shared by both
// batches; packed idx pairs give both levels in one smem read. 7:3 CSA ->
// 3-round tree (7 planes) -> chunk partial. 7th CTA of each (bp,ss) group
// sums chunks -> threshold -> enc -> coalesced classify. 40th group
// completion writes out. Deterministic; int atomics only.
// ---------------------------------------------------------------------------
__global__ void __launch_bounds__(256) hdc_main_kernel(const float* __restrict__ cw,
                                                       float* __restrict__ out)
{
    const int bp   = blockIdx.x / (NSS * NCH);
    const int r0   = blockIdx.x - bp * (NSS * NCH);
    const int ss   = r0 / NCH;
    const int ch   = r0 - ss * NCH;
    const int grp  = bp * NSS + ss;
    const int tid  = threadIdx.x;
    const int lane = tid & 31;
    const int wsub = tid >> 5;                   // 0..7

    __shared__ uint32_t sIdx2[112];
    __shared__ uint2    sBuf[4][2][7][32];       // [src][b][plane][lane]
    __shared__ uint32_t sEnc[2][64];
    __shared__ int      sDoB, sLast;

    if (tid < 112) sIdx2[tid] = g_idx2[bp * Pn + ch * 112 + tid];
    __syncthreads();

    const int wbase = ss * 64 + 2 * lane;        // first word of lane's pair
    const int p0    = ch * 112 + wsub * 14;      // global first pixel of warp

    uint32_t cnt[2][2][4];                       // [batch][comp][plane], <=14
#pragma unroll
    for (int b = 0; b < 2; b++)
#pragma unroll
        for (int c = 0; c < 2; c++)
#pragma unroll
            for (int j = 0; j < 4; j++) cnt[b][c][j] = 0u;

#pragma unroll
    for (int g = 0; g < 2; g++) {                // 2 groups of 7 pixels
        const int pg = p0 + g * 7;
        const int lg = wsub * 14 + g * 7;        // local pixel in chunk
        uint32_t pr[7]; uint2 q[7], va[7], vb[7];
#pragma unroll
        for (int k = 0; k < 7; k++) pr[k] = sIdx2[lg + k];
#pragma unroll
        for (int k = 0; k < 7; k++)
            q[k] = __ldg(reinterpret_cast<const uint2*>(g_pbits + (pg + k) * WSTRIDE + wbase));
#pragma unroll
        for (int k = 0; k < 7; k++)
            va[k] = __ldg(reinterpret_cast<const uint2*>(g_vbits + (pr[k] & 0xffffu) * WSTRIDE + wbase));
#pragma unroll
        for (int k = 0; k < 7; k++)
            vb[k] = __ldg(reinterpret_cast<const uint2*>(g_vbits + (pr[k] >> 16) * WSTRIDE + wbase));

        uint32_t t[7];
#pragma unroll
        for (int k = 0; k < 7; k++) t[k] = va[k].x ^ q[k].x;
        csa7_merge4(t, cnt[0][0]);
#pragma unroll
        for (int k = 0; k < 7; k++) t[k] = va[k].y ^ q[k].y;
        csa7_merge4(t, cnt[0][1]);
#pragma unroll
        for (int k = 0; k < 7; k++) t[k] = vb[k].x ^ q[k].x;
        csa7_merge4(t, cnt[1][0]);
#pragma unroll
        for (int k = 0; k < 7; k++) t[k] = vb[k].y ^ q[k].y;
        csa7_merge4(t, cnt[1][1]);
    }

    // ---- 3-round tree reduction across 8 warps: 4 -> 7 planes ----
    uint32_t a[2][2][7];
#pragma unroll
    for (int b = 0; b < 2; b++)
#pragma unroll
        for (int c = 0; c < 2; c++) {
#pragma unroll
            for (int j = 0; j < 4; j++) a[b][c][j] = cnt[b][c][j];
            a[b][c][4] = a[b][c][5] = a[b][c][6] = 0u;
        }

#pragma unroll
    for (int r = 0; r < 3; r++) {
        const int half = 4 >> r;                 // 4,2,1 readers
        const int np   = 4 + r;                  // planes valid in sources
        if (wsub >= half && wsub < 2 * half) {
#pragma unroll
            for (int b = 0; b < 2; b++)
#pragma unroll
                for (int j = 0; j < 7; j++)
                    if (j < np)
                        sBuf[wsub - half][b][j][lane] = make_uint2(a[b][0][j], a[b][1][j]);
        }
        __syncthreads();
        if (wsub < half) {
#pragma unroll
            for (int b = 0; b < 2; b++) {
                uint32_t cx = 0u, cy = 0u;
#pragma unroll
                for (int j = 0; j < 7; j++) {
                    if (j < np) {
                        uint2 v = sBuf[wsub][b][j][lane];
                        uint32_t s, co;
                        fadd(a[b][0][j], v.x, cx, s, co); a[b][0][j] = s; cx = co;
                        fadd(a[b][1][j], v.y, cy, s, co); a[b][1][j] = s; cy = co;
                    } else if (j == np) {
                        a[b][0][j] = cx; a[b][1][j] = cy;
                    }
                }
            }
        }
        __syncthreads();
    }

    if (wsub == 0) {                             // write 7-plane chunk partial
#pragma unroll
        for (int b = 0; b < 2; b++)
#pragma unroll
            for (int j = 0; j < 7; j++)
                g_chunk[(((grp * NCH + ch) * 2 + b) * 7 + j) * 32 + lane] =
                    make_uint2(a[b][0][j], a[b][1][j]);
    }
    __syncthreads();

    // ---- group arrival: 7th CTA of this (bp,ss) runs phase B ----
    if (tid == 0) {
        __threadfence();
        int prev = atomicAdd(&g_gctr[grp], 1);
        sDoB = (prev == NCH - 1);
        if (sDoB) g_gctr[grp] = 0;               // reset for next replay
    }
    __syncthreads();
    if (!sDoB) return;

    __threadfence();                             // acquire peer chunk partials

    // ---- phase B: warps 0,1 (one per batch) sum 7 chunks -> enc ----
    if (wsub < 2) {
        uint32_t s[2][10];
#pragma unroll
        for (int c = 0; c < 2; c++)
#pragma unroll
            for (int j = 0; j < 10; j++) s[c][j] = 0u;
#pragma unroll
        for (int c2 = 0; c2 < NCH; c2++) {
            const int uc = grp * NCH + c2;       // chunk-partial slot
            uint32_t cx = 0u, cy = 0u;
#pragma unroll
            for (int j = 0; j < 7; j++) {
                uint2 v = g_chunk[((uc * 2 + wsub) * 7 + j) * 32 + lane];
                uint32_t ss2, co;
                fadd(s[0][j], v.x, cx, ss2, co); s[0][j] = ss2; cx = co;
                fadd(s[1][j], v.y, cy, ss2, co); s[1][j] = ss2; cy = co;
            }
#pragma unroll
            for (int j = 7; j < 10; j++) {
                uint32_t nc = s[0][j] ^ cx; cx &= s[0][j]; s[0][j] = nc;
                nc = s[1][j] ^ cy; cy &= s[1][j]; s[1][j] = nc;
            }
        }
        sEnc[wsub][2 * lane]     = thr392(s[0]);
        sEnc[wsub][2 * lane + 1] = thr392(s[1]);
    }
    __syncthreads();

    // ---- coalesced classify: uu = b*10+c over dims [ss*2048, +2048) ----
    for (int uu = wsub; uu < 2 * Cn; uu += 8) {
        const int b = uu / Cn, c = uu - (uu / Cn) * Cn;
        const float* __restrict__ wrow = cw + c * Dn + ss * 2048;
        float acc = 0.0f;
#pragma unroll
        for (int i = 0; i < 16; i++) {
            int d0 = ss * 2048 + i * 128 + lane * 4;
            if (d0 < Dn) {                       // Dn%4==0 -> whole float4 valid
                uint32_t w0 = sEnc[b][i * 4 + 0];
                uint32_t w1 = sEnc[b][i * 4 + 1];
                uint32_t w2 = sEnc[b][i * 4 + 2];
                uint32_t w3 = sEnc[b][i * 4 + 3];
                float4 v = *reinterpret_cast<const float4*>(wrow + i * 128 + lane * 4);
                acc += ((w0 >> lane) & 1u) ? v.x : -v.x;
                acc += ((w1 >> lane) & 1u) ? v.y : -v.y;
                acc += ((w2 >> lane) & 1u) ? v.z : -v.z;
                acc += ((w3 >> lane) & 1u) ? v.w : -v.w;
            }
        }
#pragma unroll
        for (int off = 16; off >= 1; off >>= 1)  // deterministic fixed order
            acc += __shfl_xor_sync(0xffffffffu, acc, off);
        if (lane == 0) g_partial[(ss * Bn + (bp * 2 + b)) * Cn + c] = acc;
    }

    // ---- 40th group completion writes the final output ----
    __syncthreads();
    if (tid == 0) {
        __threadfence();
        int prev = atomicAdd(&g_ctr2, 1);
        sLast = (prev == NGROUP - 1);
    }
    __syncthreads();
    if (sLast) {
        __threadfence();
        if (tid < Bn * Cn) {
            float s = 0.0f;
#pragma unroll
            for (int sl = 0; sl < NSS; sl++) s += g_partial[sl * Bn * Cn + tid];
            out[tid] = s;
        }
        if (tid == 0) g_ctr2 = 0;                // reset for next replay
    }
}

// ---------------------------------------------------------------------------
extern "C" void kernel_launch(void* const* d_in, const int* in_sizes, int n_in,
                              void* d_out, int out_size)
{
    const float* x    = (const float*)d_in[0];   // [16,28,28]
    const float* posw = (const float*)d_in[1];   // [784,10000]
    const float* valw = (const float*)d_in[2];   // [1000,10000]
    const float* cw   = (const float*)d_in[3];   // [10,10000]
    float* out = (float*)d_out;                  // [16,10]

    pack_kernel<<<1184, 256>>>(x, posw, valw);
    hdc_main_kernel<<<NMAIN, 256>>>(cw, out);
}

// round 17
// speedup vs baseline: 2.8340x; 1.0380x over previous
#include <cuda_runtime.h>
#include <stdint.h>

// Problem constants (fixed by the reference setup)
#define Bn 16
#define Pn 784
#define Dn 10000
#define Ln 1000
#define Cn 10

#define WSTRIDE 320    // padded words per row
#define NSS     5      // 5 superslabs of 64 words
#define NCH     7      // 7 pixel chunks of 112 (8 warps x 14)
#define NBP     8      // 8 batch pairs
#define NGROUP  (NBP * NSS)          // 40 (bp, ss) groups
#define NMAIN   (NGROUP * NCH)       // 280 main CTAs

// Scratch (allocation-free: device globals)
__device__ uint32_t g_vbits[Ln * WSTRIDE];     // sign bits of value_weight
__device__ uint32_t g_pbits[Pn * WSTRIDE];     // sign bits of position_weight
__device__ uint32_t g_idx2[NBP * Pn];          // packed level idx pair (lo|hi<<16)
__device__ uint2    g_chunk[NMAIN * 2 * 7 * 32]; // 7-plane chunk partials
__device__ float    g_partial[NSS * Bn * Cn];
__device__ int      g_gctr[NGROUP];            // per-group arrival counters
__device__ int      g_ctr2;                    // group completion counter

// ---------------------------------------------------------------------------
// Kernel 1: packed idx pairs + sign packing of both bipolar tables.
// Permuted bit layout: word w, bit l  <->  dim d = (w>>2)*128 + l*4 + (w&3).
// Warp-task = 512 dims: 4 lane-contiguous float4 loads (fully coalesced),
// FSETP feeding VOTE directly, 16 ballots -> 16 words, 64B store.
// ---------------------------------------------------------------------------
__global__ void __launch_bounds__(256) pack_kernel(const float* __restrict__ x,
                                                   const float* __restrict__ posw,
                                                   const float* __restrict__ valw)
{
    const int tid     = blockIdx.x * blockDim.x + threadIdx.x;
    const int nthread = gridDim.x * blockDim.x;

    // packed level indices: idx = clamp(rint(x*999), 0, 999)  (half-to-even)
    for (int i = tid; i < NBP * Pn; i += nthread) {
        int bp = i / Pn, p = i - bp * Pn;
        int qa = (int)rintf(x[(2 * bp)     * Pn + p] * 999.0f);
        int qb = (int)rintf(x[(2 * bp + 1) * Pn + p] * 999.0f);
        qa = min(max(qa, 0), Ln - 1);
        qb = min(max(qb, 0), Ln - 1);
        g_idx2[i] = (uint32_t)qa | ((uint32_t)qb << 16);
    }

    const int lane   = threadIdx.x & 31;
    const int warpId = tid >> 5;
    const int nWarps = nthread >> 5;
    const int totalTasks = (Ln + Pn) * 20;   // 20 x 512-dim tasks per row

    for (int task = warpId; task < totalTasks; task += nWarps) {
        int row = task / 20;
        int s   = task - row * 20;
        const float* src;
        uint32_t* dst;
        if (row < Ln) {
            src = valw + (size_t)row * Dn;
            dst = g_vbits + row * WSTRIDE;
        } else {
            src = posw + (size_t)(row - Ln) * Dn;
            dst = g_pbits + (row - Ln) * WSTRIDE;
        }

        uint32_t myword = 0;
        if (s < 19) {
            float4 v0 = *reinterpret_cast<const float4*>(src + s * 512 +   0 + lane * 4);
            float4 v1 = *reinterpret_cast<const float4*>(src + s * 512 + 128 + lane * 4);
            float4 v2 = *reinterpret_cast<const float4*>(src + s * 512 + 256 + lane * 4);
            float4 v3 = *reinterpret_cast<const float4*>(src + s * 512 + 384 + lane * 4);
#define PK(sub, vv)                                                          \
            {                                                                \
                uint32_t b0 = __ballot_sync(0xffffffffu, (vv).x < 0.0f);     \
                uint32_t b1 = __ballot_sync(0xffffffffu, (vv).y < 0.0f);     \
                uint32_t b2 = __ballot_sync(0xffffffffu, (vv).z < 0.0f);     \
                uint32_t b3 = __ballot_sync(0xffffffffu, (vv).w < 0.0f);     \
                if (lane == (sub)*4 + 0) myword = b0;                        \
                if (lane == (sub)*4 + 1) myword = b1;                        \
                if (lane == (sub)*4 + 2) myword = b2;                        \
                if (lane == (sub)*4 + 3) myword = b3;                        \
            }
            PK(0, v0) PK(1, v1) PK(2, v2) PK(3, v3)
#undef PK
        } else {
            // tail task (dims 9728..10239): per-lane validity
#pragma unroll
            for (int sub = 0; sub < 4; sub++) {
                int d0 = s * 512 + sub * 128 + lane * 4;
                bool valid = d0 < Dn;            // Dn % 4 == 0
                float4 v = make_float4(0.f, 0.f, 0.f, 0.f);
                if (valid) v = *reinterpret_cast<const float4*>(src + d0);
                uint32_t b0 = __ballot_sync(0xffffffffu, valid && v.x < 0.0f);
                uint32_t b1 = __ballot_sync(0xffffffffu, valid && v.y < 0.0f);
                uint32_t b2 = __ballot_sync(0xffffffffu, valid && v.z < 0.0f);
                uint32_t b3 = __ballot_sync(0xffffffffu, valid && v.w < 0.0f);
                if (lane == sub * 4 + 0) myword = b0;
                if (lane == sub * 4 + 1) myword = b1;
                if (lane == sub * 4 + 2) myword = b2;
                if (lane == sub * 4 + 3) myword = b3;
            }
        }
        if (lane < 16) dst[s * 16 + lane] = myword;      // coalesced 64B
    }
}

// ---------------------------------------------------------------------------
__device__ __forceinline__ void fadd(uint32_t a, uint32_t b, uint32_t cin,
                                     uint32_t& s, uint32_t& cout)
{
    uint32_t t = a ^ b;
    s    = t ^ cin;
    cout = (a & b) | (cin & t);
}

// 7:3 compress t[0..6] and merge into 4-plane counter cp[0..3] (max 14)
__device__ __forceinline__ void csa7_merge4(const uint32_t* t, uint32_t* cp)
{
    uint32_t s1, c1, s2, c2, s3, c3, s4, c4;
    fadd(t[0], t[1], t[2], s1, c1);
    fadd(t[3], t[4], t[5], s2, c2);
    fadd(s1,  s2,  t[6],  s3, c3);
    fadd(c1,  c2,  c3,    s4, c4);
    uint32_t carry = cp[0] & s3; cp[0] ^= s3;
    uint32_t s, co;
    fadd(cp[1], s4, carry, s, co); cp[1] = s; carry = co;
    fadd(cp[2], c4, carry, s, co); cp[2] = s; carry = co;
    cp[3] ^= carry;
}

// enc bit = 1 iff count < 392 (392 = 0b0110001000), 10 bit-planes
__device__ __forceinline__ uint32_t thr392(const uint32_t* c)
{
    uint32_t eq = ~0u, lt = 0u;
    eq &= ~c[9];
    lt |= eq & ~c[8]; eq &= c[8];
    lt |= eq & ~c[7]; eq &= c[7];
    eq &= ~c[6]; eq &= ~c[5]; eq &= ~c[4];
    lt |= eq & ~c[3];
    return lt;
}

// ---------------------------------------------------------------------------
// Kernel 2 (R11 body + 128-reg budget): CTA = (batch-pair, superslab of 64
// words, chunk of 112 pixels), 256 threads = 8 warps x 14 px. Lane holds a
// word pair (uint2, LDG.64); pbits loaded once per pixel shared by both
// batches. __launch_bounds__(256,2) raises the register budget to 128 so
// ptxas can front-batch the 21-load gather group (MLP 21) — grid is already
// <2 CTAs/SM so this costs no occupancy. 7:3 CSA -> 3-round tree -> chunk
// partial; 7th CTA of each group: threshold + coalesced classify; 40th
// group completion writes out. Deterministic; int atomics only.
// ---------------------------------------------------------------------------
__global__ void __launch_bounds__(256, 2) hdc_main_kernel(const float* __restrict__ cw,
                                                          float* __restrict__ out)
{
    const int bp   = blockIdx.x / (NSS * NCH);
    const int r0   = blockIdx.x - bp * (NSS * NCH);
    const int ss   = r0 / NCH;
    const int ch   = r0 - ss * NCH;
    const int grp  = bp * NSS + ss;
    const int tid  = threadIdx.x;
    const int lane = tid & 31;
    const int wsub = tid >> 5;                   // 0..7

    __shared__ uint32_t sIdx2[112];
    __shared__ uint2    sBuf[4][2][7][32];       // [src][b][plane][lane]
    __shared__ uint32_t sEnc[2][64];
    __shared__ int      sDoB, sLast;

    if (tid < 112) sIdx2[tid] = g_idx2[bp * Pn + ch * 112 + tid];
    __syncthreads();

    const int wbase = ss * 64 + 2 * lane;        // first word of lane's pair
    const int p0    = ch * 112 + wsub * 14;      // global first pixel of warp

    uint32_t cnt[2][2][4];                       // [batch][comp][plane], <=14
#pragma unroll
    for (int b = 0; b < 2; b++)
#pragma unroll
        for (int c = 0; c < 2; c++)
#pragma unroll
            for (int j = 0; j < 4; j++) cnt[b][c][j] = 0u;

#pragma unroll
    for (int g = 0; g < 2; g++) {                // 2 groups of 7 pixels
        const int pg = p0 + g * 7;
        const int lg = wsub * 14 + g * 7;        // local pixel in chunk
        uint32_t pr[7]; uint2 q[7], va[7], vb[7];
#pragma unroll
        for (int k = 0; k < 7; k++) pr[k] = sIdx2[lg + k];
#pragma unroll
        for (int k = 0; k < 7; k++)
            q[k] = __ldg(reinterpret_cast<const uint2*>(g_pbits + (pg + k) * WSTRIDE + wbase));
#pragma unroll
        for (int k = 0; k < 7; k++)
            va[k] = __ldg(reinterpret_cast<const uint2*>(g_vbits + (pr[k] & 0xffffu) * WSTRIDE + wbase));
#pragma unroll
        for (int k = 0; k < 7; k++)
            vb[k] = __ldg(reinterpret_cast<const uint2*>(g_vbits + (pr[k] >> 16) * WSTRIDE + wbase));

        uint32_t t[7];
#pragma unroll
        for (int k = 0; k < 7; k++) t[k] = va[k].x ^ q[k].x;
        csa7_merge4(t, cnt[0][0]);
#pragma unroll
        for (int k = 0; k < 7; k++) t[k] = va[k].y ^ q[k].y;
        csa7_merge4(t, cnt[0][1]);
#pragma unroll
        for (int k = 0; k < 7; k++) t[k] = vb[k].x ^ q[k].x;
        csa7_merge4(t, cnt[1][0]);
#pragma unroll
        for (int k = 0; k < 7; k++) t[k] = vb[k].y ^ q[k].y;
        csa7_merge4(t, cnt[1][1]);
    }

    // ---- 3-round tree reduction across 8 warps: 4 -> 7 planes ----
    uint32_t a[2][2][7];
#pragma unroll
    for (int b = 0; b < 2; b++)
#pragma unroll
        for (int c = 0; c < 2; c++) {
#pragma unroll
            for (int j = 0; j < 4; j++) a[b][c][j] = cnt[b][c][j];
            a[b][c][4] = a[b][c][5] = a[b][c][6] = 0u;
        }

#pragma unroll
    for (int r = 0; r < 3; r++) {
        const int half = 4 >> r;                 // 4,2,1 readers
        const int np   = 4 + r;                  // planes valid in sources
        if (wsub >= half && wsub < 2 * half) {
#pragma unroll
            for (int b = 0; b < 2; b++)
#pragma unroll
                for (int j = 0; j < 7; j++)
                    if (j < np)
                        sBuf[wsub - half][b][j][lane] = make_uint2(a[b][0][j], a[b][1][j]);
        }
        __syncthreads();
        if (wsub < half) {
#pragma unroll
            for (int b = 0; b < 2; b++) {
                uint32_t cx = 0u, cy = 0u;
#pragma unroll
                for (int j = 0; j < 7; j++) {
                    if (j < np) {
                        uint2 v = sBuf[wsub][b][j][lane];
                        uint32_t s, co;
                        fadd(a[b][0][j], v.x, cx, s, co); a[b][0][j] = s; cx = co;
                        fadd(a[b][1][j], v.y, cy, s, co); a[b][1][j] = s; cy = co;
                    } else if (j == np) {
                        a[b][0][j] = cx; a[b][1][j] = cy;
                    }
                }
            }
        }
        __syncthreads();
    }

    if (wsub == 0) {                             // write 7-plane chunk partial
#pragma unroll
        for (int b = 0; b < 2; b++)
#pragma unroll
            for (int j = 0; j < 7; j++)
                g_chunk[(((grp * NCH + ch) * 2 + b) * 7 + j) * 32 + lane] =
                    make_uint2(a[b][0][j], a[b][1][j]);
    }
    __syncthreads();

    // ---- group arrival: 7th CTA of this (bp,ss) runs phase B ----
    if (tid == 0) {
        __threadfence();
        int prev = atomicAdd(&g_gctr[grp], 1);
        sDoB = (prev == NCH - 1);
        if (sDoB) g_gctr[grp] = 0;               // reset for next replay
    }
    __syncthreads();
    if (!sDoB) return;

    __threadfence();                             // acquire peer chunk partials

    // ---- phase B: warps 0,1 (one per batch) sum 7 chunks -> enc ----
    if (wsub < 2) {
        uint32_t s[2][10];
#pragma unroll
        for (int c = 0; c < 2; c++)
#pragma unroll
            for (int j = 0; j < 10; j++) s[c][j] = 0u;
#pragma unroll
        for (int c2 = 0; c2 < NCH; c2++) {
            const int uc = grp * NCH + c2;       // chunk-partial slot
            uint32_t cx = 0u, cy = 0u;
#pragma unroll
            for (int j = 0; j < 7; j++) {
                uint2 v = g_chunk[((uc * 2 + wsub) * 7 + j) * 32 + lane];
                uint32_t ss2, co;
                fadd(s[0][j], v.x, cx, ss2, co); s[0][j] = ss2; cx = co;
                fadd(s[1][j], v.y, cy, ss2, co); s[1][j] = ss2; cy = co;
            }
#pragma unroll
            for (int j = 7; j < 10; j++) {
                uint32_t nc = s[0][j] ^ cx; cx &= s[0][j]; s[0][j] = nc;
                nc = s[1][j] ^ cy; cy &= s[1][j]; s[1][j] = nc;
            }
        }
        sEnc[wsub][2 * lane]     = thr392(s[0]);
        sEnc[wsub][2 * lane + 1] = thr392(s[1]);
    }
    __syncthreads();

    // ---- coalesced classify: uu = b*10+c over dims [ss*2048, +2048) ----
    for (int uu = wsub; uu < 2 * Cn; uu += 8) {
        const int b = uu / Cn, c = uu - (uu / Cn) * Cn;
        const float* __restrict__ wrow = cw + c * Dn + ss * 2048;
        float acc = 0.0f;
#pragma unroll
        for (int i = 0; i < 16; i++) {
            int d0 = ss * 2048 + i * 128 + lane * 4;
            if (d0 < Dn) {                       // Dn%4==0 -> whole float4 valid
                uint32_t w0 = sEnc[b][i * 4 + 0];
                uint32_t w1 = sEnc[b][i * 4 + 1];
                uint32_t w2 = sEnc[b][i * 4 + 2];
                uint32_t w3 = sEnc[b][i * 4 + 3];
                float4 v = *reinterpret_cast<const float4*>(wrow + i * 128 + lane * 4);
                acc += ((w0 >> lane) & 1u) ? v.x : -v.x;
                acc += ((w1 >> lane) & 1u) ? v.y : -v.y;
                acc += ((w2 >> lane) & 1u) ? v.z : -v.z;
                acc += ((w3 >> lane) & 1u) ? v.w : -v.w;
            }
        }
#pragma unroll
        for (int off = 16; off >= 1; off >>= 1)  // deterministic fixed order
            acc += __shfl_xor_sync(0xffffffffu, acc, off);
        if (lane == 0) g_partial[(ss * Bn + (bp * 2 + b)) * Cn + c] = acc;
    }

    // ---- 40th group completion writes the final output ----
    __syncthreads();
    if (tid == 0) {
        __threadfence();
        int prev = atomicAdd(&g_ctr2, 1);
        sLast = (prev == NGROUP - 1);
    }
    __syncthreads();
    if (sLast) {
        __threadfence();
        if (tid < Bn * Cn) {
            float s = 0.0f;
#pragma unroll
            for (int sl = 0; sl < NSS; sl++) s += g_partial[sl * Bn * Cn + tid];
            out[tid] = s;
        }
        if (tid == 0) g_ctr2 = 0;                // reset for next replay
    }
}

// ---------------------------------------------------------------------------
extern "C" void kernel_launch(void* const* d_in, const int* in_sizes, int n_in,
                              void* d_out, int out_size)
{
    const float* x    = (const float*)d_in[0];   // [16,28,28]
    const float* posw = (const float*)d_in[1];   // [784,10000]
    const float* valw = (const float*)d_in[2];   // [1000,10000]
    const float* cw   = (const float*)d_in[3];   // [10,10000]
    float* out = (float*)d_out;                  // [16,10]

    pack_kernel<<<1184, 256>>>(x, posw, valw);
    hdc_main_kernel<<<NMAIN, 256>>>(cw, out);
}